// round 3
// baseline (speedup 1.0000x reference)
#include <cuda_runtime.h>

#define TIMES 4

// Each thread processes 2 float4 lanes (32 bytes) per time-step.
// Lanes are warp-contiguous: thread i handles float4 indices (2*blockbase + tid)
// and (2*blockbase + tid + blockDim) so each warp's accesses stay fully coalesced.
__global__ __launch_bounds__(256) void spike_kernel2(
    const float4* __restrict__ in, float4* __restrict__ out, int n_per_chunk /* float4 count */)
{
    int base = blockIdx.x * (blockDim.x * 2) + threadIdx.x;
    int iA = base;                 // first lane
    int iB = base + blockDim.x;    // second lane (coalesced with neighbors)
    if (iB >= n_per_chunk) {       // exact sizes divide evenly; guard anyway
        if (iA >= n_per_chunk) return;
        iB = iA; // degenerate; harmless duplicate work on ragged tail
    }

    // Front-batch all 8 independent streaming loads (MLP=8).
    float4 A0 = __ldcs(&in[(size_t)0 * n_per_chunk + iA]);
    float4 B0 = __ldcs(&in[(size_t)0 * n_per_chunk + iB]);
    float4 A1 = __ldcs(&in[(size_t)1 * n_per_chunk + iA]);
    float4 B1 = __ldcs(&in[(size_t)1 * n_per_chunk + iB]);
    float4 A2 = __ldcs(&in[(size_t)2 * n_per_chunk + iA]);
    float4 B2 = __ldcs(&in[(size_t)2 * n_per_chunk + iB]);
    float4 A3 = __ldcs(&in[(size_t)3 * n_per_chunk + iA]);
    float4 B3 = __ldcs(&in[(size_t)3 * n_per_chunk + iB]);

    float4 VA = make_float4(0.f, 0.f, 0.f, 0.f);
    float4 VB = make_float4(0.f, 0.f, 0.f, 0.f);

    #define STEP(V, I)                                               \
        V.x += (I).x; V.y += (I).y; V.z += (I).z; V.w += (I).w;      \
        V.x = (fabsf(V.x) > 1.0f) ? 0.0f : V.x;                      \
        V.y = (fabsf(V.y) > 1.0f) ? 0.0f : V.y;                      \
        V.z = (fabsf(V.z) > 1.0f) ? 0.0f : V.z;                      \
        V.w = (fabsf(V.w) > 1.0f) ? 0.0f : V.w;

    STEP(VA, A0); __stcs(&out[(size_t)0 * n_per_chunk + iA], VA);
    STEP(VB, B0); __stcs(&out[(size_t)0 * n_per_chunk + iB], VB);
    STEP(VA, A1); __stcs(&out[(size_t)1 * n_per_chunk + iA], VA);
    STEP(VB, B1); __stcs(&out[(size_t)1 * n_per_chunk + iB], VB);
    STEP(VA, A2); __stcs(&out[(size_t)2 * n_per_chunk + iA], VA);
    STEP(VB, B2); __stcs(&out[(size_t)2 * n_per_chunk + iB], VB);
    STEP(VA, A3); __stcs(&out[(size_t)3 * n_per_chunk + iA], VA);
    STEP(VB, B3); __stcs(&out[(size_t)3 * n_per_chunk + iB], VB);

    #undef STEP
}

extern "C" void kernel_launch(void* const* d_in, const int* in_sizes, int n_in,
                              void* d_out, int out_size) {
    const float4* in = (const float4*)d_in[0];
    float4* out = (float4*)d_out;
    int n_per_chunk = out_size / TIMES / 4;     // float4 elements per chunk (4,194,304)
    int threads = 256;
    int per_block = threads * 2;                // 2 float4 per thread
    int blocks = (n_per_chunk + per_block - 1) / per_block;
    spike_kernel2<<<blocks, threads>>>(in, out, n_per_chunk);
}

// round 4
// speedup vs baseline: 1.0163x; 1.0163x over previous
#include <cuda_runtime.h>

#define TIMES 4

// One float4 (16B) per thread per time-step. 4 independent front-batched
// streaming loads (MLP=4 — empirically sufficient to saturate HBM at
// occ~78%), dependent accumulate/reset chain, streaming stores.
// __ldcs/__stcs: both streams are single-touch; don't retain in L2.
__global__ __launch_bounds__(256) void spike_kernel(
    const float4* __restrict__ in, float4* __restrict__ out, int n_per_chunk /* float4 count */)
{
    int i = blockIdx.x * blockDim.x + threadIdx.x;
    if (i >= n_per_chunk) return;

    float4 I0 = __ldcs(&in[(size_t)0 * n_per_chunk + i]);
    float4 I1 = __ldcs(&in[(size_t)1 * n_per_chunk + i]);
    float4 I2 = __ldcs(&in[(size_t)2 * n_per_chunk + i]);
    float4 I3 = __ldcs(&in[(size_t)3 * n_per_chunk + i]);

    float4 V = make_float4(0.f, 0.f, 0.f, 0.f);

    #define STEP(I)                                                  \
        V.x += (I).x; V.y += (I).y; V.z += (I).z; V.w += (I).w;      \
        V.x = (fabsf(V.x) > 1.0f) ? 0.0f : V.x;                      \
        V.y = (fabsf(V.y) > 1.0f) ? 0.0f : V.y;                      \
        V.z = (fabsf(V.z) > 1.0f) ? 0.0f : V.z;                      \
        V.w = (fabsf(V.w) > 1.0f) ? 0.0f : V.w;

    STEP(I0); __stcs(&out[(size_t)0 * n_per_chunk + i], V);
    STEP(I1); __stcs(&out[(size_t)1 * n_per_chunk + i], V);
    STEP(I2); __stcs(&out[(size_t)2 * n_per_chunk + i], V);
    STEP(I3); __stcs(&out[(size_t)3 * n_per_chunk + i], V);

    #undef STEP
}

extern "C" void kernel_launch(void* const* d_in, const int* in_sizes, int n_in,
                              void* d_out, int out_size) {
    const float4* in = (const float4*)d_in[0];
    float4* out = (float4*)d_out;
    int n_per_chunk = out_size / TIMES / 4;  // float4 elements per chunk (4,194,304)
    int threads = 256;
    int blocks = (n_per_chunk + threads - 1) / threads;
    spike_kernel<<<blocks, threads>>>(in, out, n_per_chunk);
}